// round 17
// baseline (speedup 1.0000x reference)
#include <cuda_runtime.h>
#include <cstdint>
#include <math.h>

#define TOPK 8
#define NSPECIAL 999
#define DDIM 768
#define SPLIT 16
#define NT0 1024         // kernel-0 single-block compaction
#define NT1 128          // kernel-1 block (per-segment top-8)
#define NT2 512          // kernel-2 block (merge + score), 2 warps per candidate
#define MAXPOS 4096
#define V4PT 4           // float4 regs per thread: covers seg_len <= 2048
#define CAP 512          // smem candidate capacity (overflow -> exact fallback)

// scratch
__device__ float g_cv[MAXPOS * SPLIT * TOPK];
__device__ int   g_ci[MAXPOS * SPLIT * TOPK];
__device__ int   g_wl[MAXPOS];   // compacted heavy (swap) positions
__device__ int   g_cnt;          // number of heavy positions

// jax.lax.top_k ordering: higher value first; ties -> lower index first.
__device__ __forceinline__ bool better(float v1, int i1, float v2, int i2) {
    return (v1 > v2) || (v1 == v2 && i1 < i2);
}

__device__ __forceinline__ void ins8(float v, int i, float lv[TOPK], int li[TOPK]) {
    if (!better(v, i, lv[TOPK - 1], li[TOPK - 1])) return;
    lv[TOPK - 1] = v; li[TOPK - 1] = i;
#pragma unroll
    for (int k = TOPK - 1; k > 0; k--) {
        if (better(lv[k], li[k], lv[k - 1], li[k - 1])) {
            float tv = lv[k]; lv[k] = lv[k - 1]; lv[k - 1] = tv;
            int   ti = li[k]; li[k] = li[k - 1]; li[k - 1] = ti;
        } else break;
    }
}

// ---------------- kernel 0: swap mask, non-swap writeout, worklist compaction ----------------
__global__ __launch_bounds__(NT0)
void swap_compact_kernel(const int*   __restrict__ tok,
                         const float* __restrict__ ru,
                         float*       __restrict__ out,
                         int BS)
{
    __shared__ int s_cnt;
    const int tid = threadIdx.x;
    if (tid == 0) s_cnt = 0;
    __syncthreads();

    for (int i = tid; i < BS; i += NT0) {
        int   st = tok[i];
        float r  = ru[i];
        bool swap = (st >= NSPECIAL) && (r > 0.7f);
        if (swap) {
            int s = atomicAdd(&s_cnt, 1);
            g_wl[s] = i;
        } else {
            out[i] = (float)st;
        }
    }
    __syncthreads();
    if (tid == 0) g_cnt = s_cnt;
}

// ---------------- kernel 1: per-heavy-position per-segment exact top-8 ----------------
__global__ __launch_bounds__(NT1)
void topk_seg_kernel(const float* __restrict__ lm,   // [BS, V]
                     int V, int seg_len)
{
    const int widx = blockIdx.x;
    const int cnt  = g_cnt;           // L2-broadcast
    if (widx >= cnt) return;
    const int pos  = g_wl[widx];
    const int seg  = blockIdx.y;
    const int tid  = threadIdx.x;

    const int start = seg * seg_len;
    const int end   = min(start + seg_len, V);
    const int navail = end - start;   // even (V even, seg_len even)
    if (navail <= 0) {
        if (tid < TOPK) {
            g_cv[(pos * SPLIT + seg) * TOPK + tid] = -INFINITY;
            g_ci[(pos * SPLIT + seg) * TOPK + tid] = 0x7fffffff;
        }
        return;
    }

    __shared__ float s_gmax[NT1 / 16];
    __shared__ float s_cv[CAP];
    __shared__ int   s_ci[CAP];
    __shared__ float s_thr;
    __shared__ int   s_cnt;

    // ---- pass 1: branchless float4 register-resident load + per-thread max ----
    const size_t base = (size_t)pos * V + start;   // even; base%4 in {0,2}
    const int head2 = ((int)(base & 3)) ? 1 : 0;   // one leading float2 if phase==2
    const int nrem  = navail - 2 * head2;
    const int n4    = nrem > 0 ? (nrem >> 2) : 0;
    const int tail2 = nrem - 4 * n4;               // 0 or 2 elements

    const float4* p4 = (const float4*)(lm + base + 2 * head2);

    float4 vals[V4PT];
#pragma unroll
    for (int k = 0; k < V4PT; k++) {
        int j = tid + k * NT1;
        if (j < n4) vals[k] = __ldg(p4 + j);
        else        vals[k] = make_float4(-INFINITY, -INFINITY, -INFINITY, -INFINITY);
    }
    // head/tail float2s handled by tid 0 (guaranteed to exist in group 0)
    float2 hv = make_float2(-INFINITY, -INFINITY);
    float2 tv = make_float2(-INFINITY, -INFINITY);
    if (tid == 0) {
        if (head2) hv = __ldg((const float2*)(lm + base));
        if (tail2) tv = __ldg((const float2*)(lm + base + 2 * head2 + 4 * n4));
    }

    float tmax = fmaxf(fmaxf(hv.x, hv.y), fmaxf(tv.x, tv.y));
#pragma unroll
    for (int k = 0; k < V4PT; k++)
        tmax = fmaxf(tmax, fmaxf(fmaxf(vals[k].x, vals[k].y), fmaxf(vals[k].z, vals[k].w)));

    // ---- threshold: min of 8 group-of-16 maxes (8 distinct elements >= t
    //      => true 8th-largest >= t => all true top-8 values >= t) ----
    float gm = tmax;
#pragma unroll
    for (int o = 8; o > 0; o >>= 1)
        gm = fmaxf(gm, __shfl_down_sync(0xffffffffu, gm, o, 16));
    if ((tid & 15) == 0) s_gmax[tid >> 4] = gm;
    if (tid == 0) s_cnt = 0;
    __syncthreads();
    if (tid == 0) {
        float t = s_gmax[0];
#pragma unroll
        for (int g = 1; g < NT1 / 16; g++) t = fminf(t, s_gmax[g]);
        s_thr = t;
    }
    __syncthreads();
    const float t = s_thr;

    // ---- pass 2: compact candidates >= t from registers (rare pushes) ----
    const int ebase = start + 2 * head2;
#pragma unroll
    for (int k = 0; k < V4PT; k++) {
        int j = tid + k * NT1;
        if (j < n4) {
            float4 p = vals[k];
            float m = fmaxf(fmaxf(p.x, p.y), fmaxf(p.z, p.w));
            if (m >= t) {
                int bi = ebase + 4 * j;
                if (p.x >= t) { int s = atomicAdd(&s_cnt, 1); if (s < CAP) { s_cv[s] = p.x; s_ci[s] = bi;     } }
                if (p.y >= t) { int s = atomicAdd(&s_cnt, 1); if (s < CAP) { s_cv[s] = p.y; s_ci[s] = bi + 1; } }
                if (p.z >= t) { int s = atomicAdd(&s_cnt, 1); if (s < CAP) { s_cv[s] = p.z; s_ci[s] = bi + 2; } }
                if (p.w >= t) { int s = atomicAdd(&s_cnt, 1); if (s < CAP) { s_cv[s] = p.w; s_ci[s] = bi + 3; } }
            }
        }
    }
    if (tid == 0) {
        if (hv.x >= t) { int s = atomicAdd(&s_cnt, 1); if (s < CAP) { s_cv[s] = hv.x; s_ci[s] = start;     } }
        if (hv.y >= t) { int s = atomicAdd(&s_cnt, 1); if (s < CAP) { s_cv[s] = hv.y; s_ci[s] = start + 1; } }
        int tb = ebase + 4 * n4;
        if (tv.x >= t) { int s = atomicAdd(&s_cnt, 1); if (s < CAP) { s_cv[s] = tv.x; s_ci[s] = tb;     } }
        if (tv.y >= t) { int s = atomicAdd(&s_cnt, 1); if (s < CAP) { s_cv[s] = tv.y; s_ci[s] = tb + 1; } }
    }
    __syncthreads();

    // ---- exact jax top-8 (value desc, index asc) over the candidates ----
    if (tid == 0) {
        float lv[TOPK]; int li[TOPK];
#pragma unroll
        for (int k = 0; k < TOPK; k++) { lv[k] = -INFINITY; li[k] = 0x7fffffff; }
        const int c = s_cnt;
        if (c <= CAP) {
            for (int i = 0; i < c; i++) ins8(s_cv[i], s_ci[i], lv, li);
        } else {
            // exact overflow fallback: serial rescan in index order
            for (int i = 0; i < navail; i++) {
                float v = __ldg(lm + base + i);
                if (v >= t) ins8(v, start + i, lv, li);
            }
        }
        float* ov = g_cv + (pos * SPLIT + seg) * TOPK;
        int*   oi = g_ci + (pos * SPLIT + seg) * TOPK;
#pragma unroll
        for (int k = 0; k < TOPK; k++) { ov[k] = lv[k]; oi[k] = li[k]; }
    }
}

// ---------------- kernel 2: merge segments + score + argmax (heavy positions only) ----------------
__global__ __launch_bounds__(NT2)
void dvat_final_kernel(const float* __restrict__ dgrad,
                       const float* __restrict__ semb,
                       const float* __restrict__ emb,
                       const int*   __restrict__ tok,
                       const int*   __restrict__ amask,
                       float*       __restrict__ out)
{
    const int widx = blockIdx.x;
    const int cnt  = g_cnt;
    if (widx >= cnt) return;
    const int pos  = g_wl[widx];
    const int tid  = threadIdx.x;
    const int st   = tok[pos];

    __shared__ __align__(16) float s_dg[DDIM];
    __shared__ __align__(16) float s_sr[DDIM];
    __shared__ float s_cv[SPLIT * TOPK];
    __shared__ int   s_ci[SPLIT * TOPK];
    __shared__ float t8v[TOPK];
    __shared__ int   t8i[TOPK];
    __shared__ float part[16][5];      // per-warp partials: gdot,sdot,vsq,pdot,ssq
    __shared__ float cscore[TOPK];
    __shared__ int   cidx[TOPK];

    {
        const float4* g4 = (const float4*)(dgrad + (size_t)pos * DDIM);
        const float4* s4 = (const float4*)(semb  + (size_t)pos * DDIM);
        float4* sg = (float4*)s_dg;
        float4* ss = (float4*)s_sr;
        for (int j = tid; j < DDIM / 4; j += NT2) { sg[j] = g4[j]; ss[j] = s4[j]; }
    }
    if (tid < SPLIT * TOPK) {
        s_cv[tid] = g_cv[pos * SPLIT * TOPK + tid];
        s_ci[tid] = g_ci[pos * SPLIT * TOPK + tid];
    }
    __syncthreads();

    // single-thread 16-way merge of sorted lists -> global top-8 (exact jax order)
    if (tid == 0) {
        int head[SPLIT];
#pragma unroll
        for (int s = 0; s < SPLIT; s++) head[s] = 0;
#pragma unroll
        for (int k = 0; k < TOPK; k++) {
            float bv = -INFINITY; int bi = 0x7fffffff; int bs = 0;
#pragma unroll
            for (int s = 0; s < SPLIT; s++) {
                int h = head[s];
                float v = s_cv[s * TOPK + h];
                int   i = s_ci[s * TOPK + h];
                if (better(v, i, bv, bi)) { bv = v; bi = i; bs = s; }
            }
            t8v[k] = bv; t8i[k] = bi;
            head[bs] = min(head[bs] + 1, TOPK - 1);
        }
    }
    __syncthreads();

    // two warps per candidate: warp w scores candidate w>>1, half (w&1) of D
    const int am   = amask[pos];
    const int wid  = tid >> 5;
    const int lane = tid & 31;
    const int cand = wid >> 1;
    const int half = wid & 1;

    int v = t8i[cand] * am;
    const bool active = (v >= NSPECIAL && v != st);   // warp-uniform

    float gdot = 0.f, sdot = 0.f, vsq = 0.f, pdot = 0.f, ssq = 0.f;
    {
        const float4* ev = (const float4*)(emb + (size_t)max(v, 0) * DDIM);
        const float4* g4 = (const float4*)s_dg;
        const float4* s4 = (const float4*)s_sr;
#pragma unroll
        for (int it = 0; it < 3; it++) {          // 96 float4s per half
            int j = half * 96 + it * 32 + lane;
            float4 g = g4[j];
            float4 s = s4[j];
            pdot += g.x * s.x + g.y * s.y + g.z * s.z + g.w * s.w;
            ssq  += s.x * s.x + s.y * s.y + s.z * s.z + s.w * s.w;
            if (active) {
                float4 e = __ldg(ev + j);
                gdot += e.x * g.x + e.y * g.y + e.z * g.z + e.w * g.w;
                sdot += e.x * s.x + e.y * s.y + e.z * s.z + e.w * s.w;
                vsq  += e.x * e.x + e.y * e.y + e.z * e.z + e.w * e.w;
            }
        }
    }
#pragma unroll
    for (int o = 16; o > 0; o >>= 1) {
        gdot += __shfl_down_sync(0xffffffffu, gdot, o);
        sdot += __shfl_down_sync(0xffffffffu, sdot, o);
        vsq  += __shfl_down_sync(0xffffffffu, vsq,  o);
        pdot += __shfl_down_sync(0xffffffffu, pdot, o);
        ssq  += __shfl_down_sync(0xffffffffu, ssq,  o);
    }
    if (lane == 0) {
        part[wid][0] = gdot; part[wid][1] = sdot; part[wid][2] = vsq;
        part[wid][3] = pdot; part[wid][4] = ssq;
    }
    __syncthreads();

    if (tid < TOPK) {
        int k = tid;
        int vk = t8i[k] * am;
        float score = -INFINITY;
        if (vk >= NSPECIAL && vk != st) {
            float g  = part[2 * k][0] + part[2 * k + 1][0];
            float sd = part[2 * k][1] + part[2 * k + 1][1];
            float vq = part[2 * k][2] + part[2 * k + 1][2];
            float pd = part[2 * k][3] + part[2 * k + 1][3];
            float sq = part[2 * k][4] + part[2 * k + 1][4];
            float sqn = sq + vq - 2.0f * sd;
            float dn  = sqrtf(fmaxf(sqn, 0.0f) + 1e-20f);
            score = (g - pd) / dn;
        }
        cscore[k] = score; cidx[k] = vk;
    }
    __syncthreads();

    if (tid == 0) {
        float best = 0.f; int bi = 0; bool found = false;
#pragma unroll
        for (int k = 0; k < TOPK; k++) {
            float sc = cscore[k]; int vi = cidx[k];
            if (sc != -INFINITY) {
                if (!found || sc > best || (sc == best && vi < bi)) {
                    best = sc; bi = vi; found = true;
                }
            }
        }
        out[pos] = (float)(found ? bi : 0);
    }
}

extern "C" void kernel_launch(void* const* d_in, const int* in_sizes, int n_in,
                              void* d_out, int out_size) {
    // size-pattern-driven input identification (order-robust)
    int idx_lm = 0, idx_emb = 0;
    long sz_lm = -1, sz_emb = -1;
    for (int i = 0; i < n_in; i++) {
        long s = in_sizes[i];
        if (s > sz_lm) { sz_emb = sz_lm; idx_emb = idx_lm; sz_lm = s; idx_lm = i; }
        else if (s > sz_emb) { sz_emb = s; idx_emb = i; }
    }
    int mids[2], nm = 0, smalls[3], ns = 0;
    long sz_small = 0x7fffffff;
    for (int i = 0; i < n_in; i++)
        if (i != idx_lm && i != idx_emb && (long)in_sizes[i] < sz_small) sz_small = in_sizes[i];
    for (int i = 0; i < n_in; i++) {
        if (i == idx_lm || i == idx_emb) continue;
        if ((long)in_sizes[i] == sz_small) { if (ns < 3) smalls[ns++] = i; }
        else                               { if (nm < 2) mids[nm++] = i; }
    }
    int idx_dg = mids[0], idx_se = mids[1];
    int idx_tok, idx_am, idx_ru;
    if (smalls[0] == 0) { idx_am = smalls[0]; idx_ru = smalls[1]; idx_tok = smalls[2]; }
    else                { idx_tok = smalls[0]; idx_am = smalls[1]; idx_ru = smalls[2]; }

    const float* dgrad = (const float*)d_in[idx_dg];
    const float* semb  = (const float*)d_in[idx_se];
    const float* emb   = (const float*)d_in[idx_emb];
    const int*   tok   = (const int*)  d_in[idx_tok];
    const float* lm    = (const float*)d_in[idx_lm];
    const int*   am    = (const int*)  d_in[idx_am];
    const float* ru    = (const float*)d_in[idx_ru];
    float* out = (float*)d_out;

    const int BS = in_sizes[idx_tok];                   // B*S = 2048
    const int V  = (int)((long)in_sizes[idx_lm] / BS);  // 30522
    int seg_len = ((V + SPLIT - 1) / SPLIT + 1) & ~1;   // even; 1908 for V=30522

    swap_compact_kernel<<<1, NT0>>>(tok, ru, out, BS);
    dim3 g1(BS, SPLIT);
    topk_seg_kernel<<<g1, NT1>>>(lm, V, seg_len);
    dvat_final_kernel<<<BS, NT2>>>(dgrad, semb, emb, tok, am, out);
}